// round 1
// baseline (speedup 1.0000x reference)
#include <cuda_runtime.h>
#include <cstdint>
#include <math.h>

#define S_LEN 2048
#define DM    1024
#define NH    16
#define DEPTH 64
#define FF    4096
#define NT    16      // query tiles of 128
#define WIN   384     // band window per query tile

#define MODE_PLAIN 0
#define MODE_SPLIT 1
#define MODE_RES   2
#define MODE_GELU  3

// ---------------- scratch (static device memory: allowed) ----------------
__device__ __align__(256) float g_xn [S_LEN*DM];
__device__ __align__(256) float g_q  [NH*S_LEN*DEPTH];
__device__ __align__(256) float g_k  [NH*S_LEN*DEPTH];
__device__ __align__(256) float g_v  [NH*S_LEN*DEPTH];
__device__ __align__(256) float g_sc [NH*NT*128*WIN];
__device__ __align__(256) float g_ctx[S_LEN*DM];
__device__ __align__(256) float g_x2 [S_LEN*DM];
__device__ __align__(256) float g_xn2[S_LEN*DM];
__device__ __align__(256) float g_h1 [S_LEN*FF];

// ---------------- helpers ----------------
__device__ __forceinline__ uint32_t f2tf(float f) {
    uint32_t r;
    asm("cvt.rna.tf32.f32 %0, %1;" : "=r"(r) : "f"(f));
    return r;
}
__device__ __forceinline__ void cp16(uint32_t dst, const void* src) {
    asm volatile("cp.async.cg.shared.global [%0], [%1], 16;\n" :: "r"(dst), "l"(src));
}
__device__ __forceinline__ void mma_tf32(float* d, const uint32_t* a, const uint32_t* b) {
    asm volatile(
        "mma.sync.aligned.m16n8k8.row.col.f32.tf32.tf32.f32 "
        "{%0,%1,%2,%3},{%4,%5,%6,%7},{%8,%9},{%0,%1,%2,%3};\n"
        : "+f"(d[0]), "+f"(d[1]), "+f"(d[2]), "+f"(d[3])
        : "r"(a[0]), "r"(a[1]), "r"(a[2]), "r"(a[3]), "r"(b[0]), "r"(b[1]));
}

// ---------------- generic tf32 GEMM: C = A[M,K] @ B[K,N] + bias, + epilogue mode ----------------
__global__ __launch_bounds__(256) void gemm_tf32(
    const float* __restrict__ A, const float* __restrict__ B,
    const float* __restrict__ bias, const float* __restrict__ res,
    float* __restrict__ C, int M, int N, int K, int mode)
{
    __shared__ float As[2][128][20];   // [buf][m][k], pad 20 -> conflict-free frag loads
    __shared__ float Bs[2][16][136];   // [buf][k][n], pad 136 -> conflict-free frag loads

    const int tid  = threadIdx.x;
    const int bm   = blockIdx.y * 128;
    const int bn   = blockIdx.x * 128;
    const int warp = tid >> 5, lane = tid & 31;
    const int wm   = (warp & 1) * 64;      // 2x4 warp grid, warp tile 64x32
    const int wn   = (warp >> 1) * 32;
    const int lq   = lane >> 2, ln = lane & 3;

    uint32_t sA = (uint32_t)__cvta_generic_to_shared(&As[0][0][0]);
    uint32_t sB = (uint32_t)__cvta_generic_to_shared(&Bs[0][0][0]);

    float acc[4][4][4];
#pragma unroll
    for (int i = 0; i < 4; ++i)
#pragma unroll
        for (int j = 0; j < 4; ++j)
#pragma unroll
            for (int e = 0; e < 4; ++e) acc[i][j][e] = 0.0f;

    const int nc = K >> 4;

#define LOADTILES(bu, kof) do {                                                   \
    for (int it = 0; it < 2; ++it) {                                              \
        int idx = tid + (it << 8);                                                \
        int m = idx >> 2; int kq = (idx & 3) << 2;                                \
        cp16(sA + (uint32_t)(((bu)*128 + m)*20 + kq)*4,                           \
             A + (size_t)(bm + m)*K + (kof) + kq);                                \
    }                                                                             \
    for (int it = 0; it < 2; ++it) {                                              \
        int idx = tid + (it << 8);                                                \
        int kk = idx >> 5; int nq = (idx & 31) << 2;                              \
        cp16(sB + (uint32_t)(((bu)*16 + kk)*136 + nq)*4,                          \
             B + (size_t)((kof) + kk)*N + bn + nq);                               \
    }                                                                             \
    asm volatile("cp.async.commit_group;\n" ::);                                  \
} while (0)

    LOADTILES(0, 0);
    for (int c = 0; c < nc; ++c) {
        const int buf = c & 1;
        if (c + 1 < nc) {
            LOADTILES((c + 1) & 1, (c + 1) << 4);
            asm volatile("cp.async.wait_group 1;\n" ::);
        } else {
            asm volatile("cp.async.wait_group 0;\n" ::);
        }
        __syncthreads();

#pragma unroll
        for (int ks = 0; ks < 2; ++ks) {
            const int ko = ks << 3;
            uint32_t af[4][4], bf[4][2];
#pragma unroll
            for (int mt = 0; mt < 4; ++mt) {
                int rm = wm + mt * 16;
                af[mt][0] = f2tf(As[buf][rm + lq    ][ko + ln    ]);
                af[mt][1] = f2tf(As[buf][rm + lq + 8][ko + ln    ]);
                af[mt][2] = f2tf(As[buf][rm + lq    ][ko + ln + 4]);
                af[mt][3] = f2tf(As[buf][rm + lq + 8][ko + ln + 4]);
            }
#pragma unroll
            for (int nt = 0; nt < 4; ++nt) {
                int cn = wn + nt * 8;
                bf[nt][0] = f2tf(Bs[buf][ko + ln    ][cn + lq]);
                bf[nt][1] = f2tf(Bs[buf][ko + ln + 4][cn + lq]);
            }
#pragma unroll
            for (int mt = 0; mt < 4; ++mt)
#pragma unroll
                for (int nt = 0; nt < 4; ++nt)
                    mma_tf32(acc[mt][nt], af[mt], bf[nt]);
        }
        __syncthreads();
    }
#undef LOADTILES

#pragma unroll
    for (int mt = 0; mt < 4; ++mt) {
#pragma unroll
        for (int nt = 0; nt < 4; ++nt) {
#pragma unroll
            for (int e = 0; e < 4; ++e) {
                int row = bm + wm + mt * 16 + lq + ((e >> 1) << 3);
                int col = bn + wn + nt * 8 + (ln << 1) + (e & 1);
                float v = acc[mt][nt][e] + bias[col];
                if (mode == MODE_RES) {
                    v += res[(size_t)row * N + col];
                    C[(size_t)row * N + col] = v;
                } else if (mode == MODE_GELU) {
                    v = 0.5f * v * (1.0f + erff(v * 0.70710678118654752f));
                    C[(size_t)row * N + col] = v;
                } else if (mode == MODE_SPLIT) {
                    // [s, h*64+d] -> [h][s][d]
                    C[(size_t)((col >> 6) * S_LEN + row) * DEPTH + (col & 63)] = v;
                } else {
                    C[(size_t)row * N + col] = v;
                }
            }
        }
    }
}

// ---------------- layernorm: one block per row ----------------
__global__ __launch_bounds__(256) void ln_kernel(
    const float* __restrict__ x, const float* __restrict__ g,
    const float* __restrict__ b, float* __restrict__ out)
{
    const int row = blockIdx.x, tid = threadIdx.x;
    const int lane = tid & 31, warp = tid >> 5;
    float4 v = *(const float4*)(x + (size_t)row * DM + tid * 4);
    float s  = v.x + v.y + v.z + v.w;
    float ss = v.x * v.x + v.y * v.y + v.z * v.z + v.w * v.w;
#pragma unroll
    for (int o = 16; o; o >>= 1) {
        s  += __shfl_xor_sync(0xffffffffu, s, o);
        ss += __shfl_xor_sync(0xffffffffu, ss, o);
    }
    __shared__ float rs[8], rss[8];
    if (lane == 0) { rs[warp] = s; rss[warp] = ss; }
    __syncthreads();
    float S = 0.f, SS = 0.f;
#pragma unroll
    for (int i = 0; i < 8; ++i) { S += rs[i]; SS += rss[i]; }
    float mu  = S * (1.0f / 1024.0f);
    float var = SS * (1.0f / 1024.0f) - mu * mu;
    float r   = rsqrtf(var + 1e-5f);
    float4 gg = *(const float4*)(g + tid * 4);
    float4 bb = *(const float4*)(b + tid * 4);
    float4 o4;
    o4.x = (v.x - mu) * r * gg.x + bb.x;
    o4.y = (v.y - mu) * r * gg.y + bb.y;
    o4.z = (v.z - mu) * r * gg.z + bb.z;
    o4.w = (v.w - mu) * r * gg.w + bb.w;
    *(float4*)(out + (size_t)row * DM + tid * 4) = o4;
}

// ---------------- zero-fill attn region ----------------
__global__ void zero_kernel(float4* __restrict__ p, size_t n4)
{
    size_t i = (size_t)blockIdx.x * blockDim.x + threadIdx.x;
    size_t stride = (size_t)gridDim.x * blockDim.x;
    float4 z = make_float4(0.f, 0.f, 0.f, 0.f);
    for (; i < n4; i += stride) p[i] = z;
}

// ---------------- banded scores: S_tile = Q_tile @ K_band^T * 0.125, masked ----------------
__global__ __launch_bounds__(256) void scores_kernel(
    const float* __restrict__ qp, const float* __restrict__ kp, float* __restrict__ sc)
{
    __shared__ float Qs[32][132];   // [k][m]
    __shared__ float Ks[32][132];   // [k][n]
    const int tid = threadIdx.x;
    const int nb = blockIdx.x, t = blockIdx.y, h = blockIdx.z;
    const int j0 = t * 128 - 128;       // window start
    const int cbase = nb * 128;
    const int ti = tid >> 4, tj = tid & 15;
    float acc[8][8];
#pragma unroll
    for (int a = 0; a < 8; ++a)
#pragma unroll
        for (int b = 0; b < 8; ++b) acc[a][b] = 0.f;

    for (int k0 = 0; k0 < DEPTH; k0 += 32) {
#pragma unroll
        for (int u = 0; u < 4; ++u) {
            int idx = tid + (u << 8);
            int i = idx >> 3; int kq = (idx & 7) << 2;
            float4 val = *(const float4*)(qp + (size_t)(h * S_LEN + t * 128 + i) * DEPTH + k0 + kq);
            Qs[kq + 0][i] = val.x; Qs[kq + 1][i] = val.y;
            Qs[kq + 2][i] = val.z; Qs[kq + 3][i] = val.w;
        }
#pragma unroll
        for (int u = 0; u < 4; ++u) {
            int idx = tid + (u << 8);
            int cc = idx >> 3; int kq = (idx & 7) << 2;
            int j = j0 + cbase + cc;
            float4 val = make_float4(0.f, 0.f, 0.f, 0.f);
            if (j >= 0 && j < S_LEN)
                val = *(const float4*)(kp + (size_t)(h * S_LEN + j) * DEPTH + k0 + kq);
            Ks[kq + 0][cc] = val.x; Ks[kq + 1][cc] = val.y;
            Ks[kq + 2][cc] = val.z; Ks[kq + 3][cc] = val.w;
        }
        __syncthreads();
#pragma unroll
        for (int kk = 0; kk < 32; ++kk) {
            float4 a0 = *(const float4*)&Qs[kk][ti << 3];
            float4 a1 = *(const float4*)&Qs[kk][(ti << 3) + 4];
            float4 b0 = *(const float4*)&Ks[kk][tj << 3];
            float4 b1 = *(const float4*)&Ks[kk][(tj << 3) + 4];
            float ra[8] = {a0.x, a0.y, a0.z, a0.w, a1.x, a1.y, a1.z, a1.w};
            float rb[8] = {b0.x, b0.y, b0.z, b0.w, b1.x, b1.y, b1.z, b1.w};
#pragma unroll
            for (int a = 0; a < 8; ++a)
#pragma unroll
                for (int b = 0; b < 8; ++b) acc[a][b] += ra[a] * rb[b];
        }
        __syncthreads();
    }
#pragma unroll
    for (int a = 0; a < 8; ++a) {
#pragma unroll
        for (int b = 0; b < 8; ++b) {
            int r = (ti << 3) + a;
            int i = t * 128 + r;
            int c = cbase + (tj << 3) + b;
            int j = j0 + c;
            float s = acc[a][b] * 0.125f;
            if (j < 0 || j >= S_LEN || (i - j) > 128 || (j - i) > 128) s = -1e9f;
            sc[(size_t)((h * NT + t) * 128 + r) * WIN + c] = s;
        }
    }
}

// ---------------- softmax per window row; writes p in-place + scatters to attn ----------------
__global__ __launch_bounds__(256) void softmax_kernel(
    float* __restrict__ sc, float* __restrict__ attn, int has_attn)
{
    const int warp = threadIdx.x >> 5, lane = threadIdx.x & 31;
    const int row = blockIdx.x * 8 + warp;       // 0..32767
    const int h = row >> 11;
    const int i = row & 2047;
    float* srow = sc + (size_t)row * WIN;
    float v[12];
    float mx = -3.0e38f;
#pragma unroll
    for (int u = 0; u < 12; ++u) { v[u] = srow[lane + (u << 5)]; mx = fmaxf(mx, v[u]); }
#pragma unroll
    for (int o = 16; o; o >>= 1) mx = fmaxf(mx, __shfl_xor_sync(0xffffffffu, mx, o));
    float sum = 0.f;
#pragma unroll
    for (int u = 0; u < 12; ++u) { v[u] = expf(v[u] - mx); sum += v[u]; }
#pragma unroll
    for (int o = 16; o; o >>= 1) sum += __shfl_xor_sync(0xffffffffu, sum, o);
    const float inv = 1.0f / sum;
    const int t = i >> 7;
    const int j0 = t * 128 - 128;
#pragma unroll
    for (int u = 0; u < 12; ++u) {
        int c = lane + (u << 5);
        float p = v[u] * inv;
        srow[c] = p;   // masked/out-of-range entries are exactly 0
        if (has_attn) {
            int j = j0 + c;
            if (j >= 0 && j < S_LEN && (i - j) <= 128 && (j - i) <= 128)
                attn[(size_t)(h * S_LEN + i) * S_LEN + j] = p;
        }
    }
}

// ---------------- PV: ctx_tile = P_window @ V_band ----------------
__global__ __launch_bounds__(256) void pv_kernel(
    const float* __restrict__ sc, const float* __restrict__ vp, float* __restrict__ ctx)
{
    __shared__ float Ps[32][132];   // [k][m]
    __shared__ float Vs[32][68];    // [k][n]
    const int tid = threadIdx.x;
    const int t = blockIdx.x, h = blockIdx.y;
    const int j0 = t * 128 - 128;
    const int ti = tid >> 4, tj = tid & 15;
    float acc[8][4];
#pragma unroll
    for (int a = 0; a < 8; ++a)
#pragma unroll
        for (int b = 0; b < 4; ++b) acc[a][b] = 0.f;

    for (int k0 = 0; k0 < WIN; k0 += 32) {
#pragma unroll
        for (int u = 0; u < 4; ++u) {
            int idx = tid + (u << 8);
            int i = idx >> 3; int kq = (idx & 7) << 2;
            float4 val = *(const float4*)(sc + (size_t)((h * NT + t) * 128 + i) * WIN + k0 + kq);
            Ps[kq + 0][i] = val.x; Ps[kq + 1][i] = val.y;
            Ps[kq + 2][i] = val.z; Ps[kq + 3][i] = val.w;
        }
#pragma unroll
        for (int u = 0; u < 2; ++u) {
            int idx = tid + (u << 8);
            int kk = idx >> 4; int nq = (idx & 15) << 2;
            int j = j0 + k0 + kk;
            float4 val = make_float4(0.f, 0.f, 0.f, 0.f);
            if (j >= 0 && j < S_LEN)
                val = *(const float4*)(vp + (size_t)(h * S_LEN + j) * DEPTH + nq);
            *(float4*)&Vs[kk][nq] = val;
        }
        __syncthreads();
#pragma unroll
        for (int kk = 0; kk < 32; ++kk) {
            float4 a0 = *(const float4*)&Ps[kk][ti << 3];
            float4 a1 = *(const float4*)&Ps[kk][(ti << 3) + 4];
            float4 b  = *(const float4*)&Vs[kk][tj << 2];
            float ra[8] = {a0.x, a0.y, a0.z, a0.w, a1.x, a1.y, a1.z, a1.w};
            float rb[4] = {b.x, b.y, b.z, b.w};
#pragma unroll
            for (int a = 0; a < 8; ++a)
#pragma unroll
                for (int bb = 0; bb < 4; ++bb) acc[a][bb] += ra[a] * rb[bb];
        }
        __syncthreads();
    }
#pragma unroll
    for (int a = 0; a < 8; ++a) {
#pragma unroll
        for (int b = 0; b < 4; ++b) {
            int i = t * 128 + (ti << 3) + a;
            int n = h * DEPTH + (tj << 2) + b;
            ctx[(size_t)i * DM + n] = acc[a][b];
        }
    }
}

// ---------------- launch ----------------
extern "C" void kernel_launch(void* const* d_in, const int* in_sizes, int n_in,
                              void* d_out, int out_size)
{
    const float* x    = (const float*)d_in[0];
    const float* wqw  = (const float*)d_in[1];
    const float* wqb  = (const float*)d_in[2];
    const float* wkw  = (const float*)d_in[3];
    const float* wkb  = (const float*)d_in[4];
    const float* wvw  = (const float*)d_in[5];
    const float* wvb  = (const float*)d_in[6];
    const float* fcw  = (const float*)d_in[7];
    const float* fcb  = (const float*)d_in[8];
    const float* ff1w = (const float*)d_in[9];
    const float* ff1b = (const float*)d_in[10];
    const float* ff2w = (const float*)d_in[11];
    const float* ff2b = (const float*)d_in[12];
    const float* ln1g = (const float*)d_in[13];
    const float* ln1b = (const float*)d_in[14];
    const float* ln2g = (const float*)d_in[15];
    const float* ln2b = (const float*)d_in[16];

    float* out = (float*)d_out;
    const int has_attn = (out_size > S_LEN * DM) ? 1 : 0;
    float* attn = out + (size_t)S_LEN * DM;

    float *xn, *q, *k, *v, *sc, *ctx, *x2, *xn2, *h1;
    cudaGetSymbolAddress((void**)&xn,  g_xn);
    cudaGetSymbolAddress((void**)&q,   g_q);
    cudaGetSymbolAddress((void**)&k,   g_k);
    cudaGetSymbolAddress((void**)&v,   g_v);
    cudaGetSymbolAddress((void**)&sc,  g_sc);
    cudaGetSymbolAddress((void**)&ctx, g_ctx);
    cudaGetSymbolAddress((void**)&x2,  g_x2);
    cudaGetSymbolAddress((void**)&xn2, g_xn2);
    cudaGetSymbolAddress((void**)&h1,  g_h1);

    const dim3 gsq(DM / 128, S_LEN / 128);     // 8 x 16

    ln_kernel<<<S_LEN, 256>>>(x, ln1g, ln1b, xn);

    gemm_tf32<<<gsq, 256>>>(xn, wqw, wqb, nullptr, q, S_LEN, DM, DM, MODE_SPLIT);
    gemm_tf32<<<gsq, 256>>>(xn, wkw, wkb, nullptr, k, S_LEN, DM, DM, MODE_SPLIT);
    gemm_tf32<<<gsq, 256>>>(xn, wvw, wvb, nullptr, v, S_LEN, DM, DM, MODE_SPLIT);

    if (has_attn)
        zero_kernel<<<8192, 256>>>((float4*)attn, (size_t)NH * S_LEN * S_LEN / 4);

    scores_kernel<<<dim3(3, NT, NH), 256>>>(q, k, sc);
    softmax_kernel<<<NH * NT * 128 / 8, 256>>>(sc, attn, has_attn);
    pv_kernel<<<dim3(NT, NH), 256>>>(sc, v, ctx);

    gemm_tf32<<<gsq, 256>>>(ctx, fcw, fcb, x, x2, S_LEN, DM, DM, MODE_RES);
    ln_kernel<<<S_LEN, 256>>>(x2, ln2g, ln2b, xn2);
    gemm_tf32<<<dim3(FF / 128, S_LEN / 128), 256>>>(xn2, ff1w, ff1b, nullptr, h1, S_LEN, FF, DM, MODE_GELU);
    gemm_tf32<<<gsq, 256>>>(h1, ff2w, ff2b, x2, out, S_LEN, DM, FF, MODE_RES);
}

// round 4
// speedup vs baseline: 1.1704x; 1.1704x over previous
#include <cuda_runtime.h>
#include <cstdint>
#include <math.h>

#define S_LEN 2048
#define DM    1024
#define NH    16
#define DEPTH 64
#define FF    4096
#define NT    16      // query tiles of 128
#define WIN   384     // band window per query tile

#define MODE_SPLIT 1  // QKV: z selects weight, head-split store
#define MODE_PART  2  // split-K partial: z selects k-range, raw store
#define MODE_GELU  3  // +bias, gelu, tf32-round store

// ---------------- scratch (static device memory: allowed) ----------------
__device__ __align__(256) float g_xn  [S_LEN*DM];
__device__ __align__(256) float g_q   [NH*S_LEN*DEPTH];
__device__ __align__(256) float g_k   [NH*S_LEN*DEPTH];
__device__ __align__(256) float g_v   [NH*S_LEN*DEPTH];
__device__ __align__(256) float g_sc  [NH*NT*128*WIN];
__device__ __align__(256) float g_ctx [S_LEN*DM];
__device__ __align__(256) float g_x2  [S_LEN*DM];
__device__ __align__(256) float g_xn2 [S_LEN*DM];
__device__ __align__(256) float g_h1  [S_LEN*FF];
__device__ __align__(256) float g_part[2*S_LEN*DM];
__device__ __align__(256) float g_wq  [DM*DM];
__device__ __align__(256) float g_wk  [DM*DM];
__device__ __align__(256) float g_wv  [DM*DM];
__device__ __align__(256) float g_wfc [DM*DM];
__device__ __align__(256) float g_wf1 [DM*FF];
__device__ __align__(256) float g_wf2 [FF*DM];

// ---------------- helpers ----------------
__device__ __forceinline__ float f2tf_f(float f) {
    uint32_t r;
    asm("cvt.rna.tf32.f32 %0, %1;" : "=r"(r) : "f"(f));
    return __uint_as_float(r);
}
__device__ __forceinline__ void cp16(uint32_t dst, const void* src) {
    asm volatile("cp.async.cg.shared.global [%0], [%1], 16;\n" :: "r"(dst), "l"(src));
}
__device__ __forceinline__ void mma_tf32(float* d, const uint32_t* a, const uint32_t* b) {
    asm volatile(
        "mma.sync.aligned.m16n8k8.row.col.f32.tf32.tf32.f32 "
        "{%0,%1,%2,%3},{%4,%5,%6,%7},{%8,%9},{%0,%1,%2,%3};\n"
        : "+f"(d[0]), "+f"(d[1]), "+f"(d[2]), "+f"(d[3])
        : "r"(a[0]), "r"(a[1]), "r"(a[2]), "r"(a[3]), "r"(b[0]), "r"(b[1]));
}

// ---------------- elementwise tf32 rounding ----------------
__global__ __launch_bounds__(256) void round_kernel(const float4* __restrict__ in,
                                                    float4* __restrict__ out, int n4)
{
    int i = blockIdx.x * 256 + threadIdx.x;
    int stride = gridDim.x * 256;
    for (; i < n4; i += stride) {
        float4 v = in[i];
        v.x = f2tf_f(v.x); v.y = f2tf_f(v.y); v.z = f2tf_f(v.z); v.w = f2tf_f(v.w);
        out[i] = v;
    }
}

// ---------------- generic tf32 GEMM (operands pre-rounded to tf32) ----------------
__global__ __launch_bounds__(256, 2) void gemm_tf32(
    const float* __restrict__ A,
    const float* __restrict__ B0, const float* __restrict__ B1, const float* __restrict__ B2,
    const float* __restrict__ bias0, const float* __restrict__ bias1, const float* __restrict__ bias2,
    float* __restrict__ C0, float* __restrict__ C1, float* __restrict__ C2,
    int M, int N, int Ksub, int Kfull, int mode)
{
    __shared__ float As[2][128][20];
    __shared__ float Bs[2][16][136];

    const int tid  = threadIdx.x;
    const int bm   = blockIdx.y * 128;
    const int bn   = blockIdx.x * 128;
    const int z    = blockIdx.z;
    const int warp = tid >> 5, lane = tid & 31;
    const int wm   = (warp & 1) * 64;
    const int wn   = (warp >> 1) * 32;
    const int lq   = lane >> 2, ln = lane & 3;

    const float* B; const float* bias; float* C; int kOff = 0;
    if (mode == MODE_SPLIT) {
        B    = (z == 0) ? B0 : (z == 1) ? B1 : B2;
        bias = (z == 0) ? bias0 : (z == 1) ? bias1 : bias2;
        C    = (z == 0) ? C0 : (z == 1) ? C1 : C2;
    } else if (mode == MODE_PART) {
        B = B0; bias = bias0; C = C0 + (size_t)z * M * N; kOff = z * Ksub;
    } else {
        B = B0; bias = bias0; C = C0;
    }

    uint32_t sA = (uint32_t)__cvta_generic_to_shared(&As[0][0][0]);
    uint32_t sB = (uint32_t)__cvta_generic_to_shared(&Bs[0][0][0]);

    float acc[4][4][4];
#pragma unroll
    for (int i = 0; i < 4; ++i)
#pragma unroll
        for (int j = 0; j < 4; ++j)
#pragma unroll
            for (int e = 0; e < 4; ++e) acc[i][j][e] = 0.0f;

    const int nc = Ksub >> 4;

#define LOADTILES(bu, kof) do {                                                   \
    for (int it = 0; it < 2; ++it) {                                              \
        int idx = tid + (it << 8);                                                \
        int m = idx >> 2; int kq = (idx & 3) << 2;                                \
        cp16(sA + (uint32_t)(((bu)*128 + m)*20 + kq)*4,                           \
             A + (size_t)(bm + m)*Kfull + kOff + (kof) + kq);                     \
    }                                                                             \
    for (int it = 0; it < 2; ++it) {                                              \
        int idx = tid + (it << 8);                                                \
        int kk = idx >> 5; int nq = (idx & 31) << 2;                              \
        cp16(sB + (uint32_t)(((bu)*16 + kk)*136 + nq)*4,                          \
             B + (size_t)(kOff + (kof) + kk)*N + bn + nq);                        \
    }                                                                             \
    asm volatile("cp.async.commit_group;\n" ::);                                  \
} while (0)

    LOADTILES(0, 0);
    for (int c = 0; c < nc; ++c) {
        const int buf = c & 1;
        if (c + 1 < nc) {
            LOADTILES((c + 1) & 1, (c + 1) << 4);
            asm volatile("cp.async.wait_group 1;\n" ::);
        } else {
            asm volatile("cp.async.wait_group 0;\n" ::);
        }
        __syncthreads();

#pragma unroll
        for (int ks = 0; ks < 2; ++ks) {
            const int ko = ks << 3;
            uint32_t af[4][4], bf[4][2];
#pragma unroll
            for (int mt = 0; mt < 4; ++mt) {
                int rm = wm + mt * 16;
                af[mt][0] = __float_as_uint(As[buf][rm + lq    ][ko + ln    ]);
                af[mt][1] = __float_as_uint(As[buf][rm + lq + 8][ko + ln    ]);
                af[mt][2] = __float_as_uint(As[buf][rm + lq    ][ko + ln + 4]);
                af[mt][3] = __float_as_uint(As[buf][rm + lq + 8][ko + ln + 4]);
            }
#pragma unroll
            for (int nt = 0; nt < 4; ++nt) {
                int cn = wn + nt * 8;
                bf[nt][0] = __float_as_uint(Bs[buf][ko + ln    ][cn + lq]);
                bf[nt][1] = __float_as_uint(Bs[buf][ko + ln + 4][cn + lq]);
            }
#pragma unroll
            for (int mt = 0; mt < 4; ++mt)
#pragma unroll
                for (int nt = 0; nt < 4; ++nt)
                    mma_tf32(acc[mt][nt], af[mt], bf[nt]);
        }
        __syncthreads();
    }
#undef LOADTILES

#pragma unroll
    for (int mt = 0; mt < 4; ++mt) {
#pragma unroll
        for (int nt = 0; nt < 4; ++nt) {
#pragma unroll
            for (int e = 0; e < 4; ++e) {
                int row = bm + wm + mt * 16 + lq + ((e >> 1) << 3);
                int col = bn + wn + nt * 8 + (ln << 1) + (e & 1);
                float v = acc[mt][nt][e];
                if (mode == MODE_PART) {
                    C[(size_t)row * N + col] = v;
                } else if (mode == MODE_GELU) {
                    v += bias[col];
                    v = 0.5f * v * (1.0f + erff(v * 0.70710678118654752f));
                    C[(size_t)row * N + col] = f2tf_f(v);
                } else { // MODE_SPLIT: [s, h*64+d] -> [h][s][d]
                    v += bias[col];
                    C[(size_t)((col >> 6) * S_LEN + row) * DEPTH + (col & 63)] = v;
                }
            }
        }
    }
}

// ---------------- combine split-K parts: out = p0 + p1 + bias + res ----------------
__global__ __launch_bounds__(256) void combine_kernel(
    const float4* __restrict__ p, const float4* __restrict__ bias,
    const float4* __restrict__ res, float4* __restrict__ out, int n4, int n4cols)
{
    int i = blockIdx.x * 256 + threadIdx.x;
    int stride = gridDim.x * 256;
    for (; i < n4; i += stride) {
        float4 a = p[i], b = p[i + n4], bb = bias[i % n4cols], r = res[i];
        float4 o;
        o.x = a.x + b.x + bb.x + r.x;
        o.y = a.y + b.y + bb.y + r.y;
        o.z = a.z + b.z + bb.z + r.z;
        o.w = a.w + b.w + bb.w + r.w;
        out[i] = o;
    }
}

// ---------------- layernorm: one block per row ----------------
__global__ __launch_bounds__(256) void ln_kernel(
    const float* __restrict__ x, const float* __restrict__ g,
    const float* __restrict__ b, float* __restrict__ out)
{
    const int row = blockIdx.x, tid = threadIdx.x;
    const int lane = tid & 31, warp = tid >> 5;
    float4 v = *(const float4*)(x + (size_t)row * DM + tid * 4);
    float s  = v.x + v.y + v.z + v.w;
    float ss = v.x * v.x + v.y * v.y + v.z * v.z + v.w * v.w;
#pragma unroll
    for (int o = 16; o; o >>= 1) {
        s  += __shfl_xor_sync(0xffffffffu, s, o);
        ss += __shfl_xor_sync(0xffffffffu, ss, o);
    }
    __shared__ float rs[8], rss[8];
    if (lane == 0) { rs[warp] = s; rss[warp] = ss; }
    __syncthreads();
    float S = 0.f, SS = 0.f;
#pragma unroll
    for (int i = 0; i < 8; ++i) { S += rs[i]; SS += rss[i]; }
    float mu  = S * (1.0f / 1024.0f);
    float var = SS * (1.0f / 1024.0f) - mu * mu;
    float r   = rsqrtf(var + 1e-5f);
    float4 gg = *(const float4*)(g + tid * 4);
    float4 bb = *(const float4*)(b + tid * 4);
    float4 o4;
    o4.x = f2tf_f((v.x - mu) * r * gg.x + bb.x);
    o4.y = f2tf_f((v.y - mu) * r * gg.y + bb.y);
    o4.z = f2tf_f((v.z - mu) * r * gg.z + bb.z);
    o4.w = f2tf_f((v.w - mu) * r * gg.w + bb.w);
    *(float4*)(out + (size_t)row * DM + tid * 4) = o4;
}

// ---------------- banded scores: S_tile = Q_tile @ K_band^T * 0.125, masked ----------------
__global__ __launch_bounds__(256) void scores_kernel(
    const float* __restrict__ qp, const float* __restrict__ kp, float* __restrict__ sc)
{
    __shared__ float Qs[32][132];
    __shared__ float Ks[32][132];
    const int tid = threadIdx.x;
    const int nb = blockIdx.x, t = blockIdx.y, h = blockIdx.z;
    const int j0 = t * 128 - 128;
    const int cbase = nb * 128;
    const int ti = tid >> 4, tj = tid & 15;
    float acc[8][8];
#pragma unroll
    for (int a = 0; a < 8; ++a)
#pragma unroll
        for (int b = 0; b < 8; ++b) acc[a][b] = 0.f;

    for (int k0 = 0; k0 < DEPTH; k0 += 32) {
#pragma unroll
        for (int u = 0; u < 4; ++u) {
            int idx = tid + (u << 8);
            int i = idx >> 3; int kq = (idx & 7) << 2;
            float4 val = *(const float4*)(qp + (size_t)(h * S_LEN + t * 128 + i) * DEPTH + k0 + kq);
            Qs[kq + 0][i] = val.x; Qs[kq + 1][i] = val.y;
            Qs[kq + 2][i] = val.z; Qs[kq + 3][i] = val.w;
        }
#pragma unroll
        for (int u = 0; u < 4; ++u) {
            int idx = tid + (u << 8);
            int cc = idx >> 3; int kq = (idx & 7) << 2;
            int j = j0 + cbase + cc;
            float4 val = make_float4(0.f, 0.f, 0.f, 0.f);
            if (j >= 0 && j < S_LEN)
                val = *(const float4*)(kp + (size_t)(h * S_LEN + j) * DEPTH + k0 + kq);
            Ks[kq + 0][cc] = val.x; Ks[kq + 1][cc] = val.y;
            Ks[kq + 2][cc] = val.z; Ks[kq + 3][cc] = val.w;
        }
        __syncthreads();
#pragma unroll
        for (int kk = 0; kk < 32; ++kk) {
            float4 a0 = *(const float4*)&Qs[kk][ti << 3];
            float4 a1 = *(const float4*)&Qs[kk][(ti << 3) + 4];
            float4 b0 = *(const float4*)&Ks[kk][tj << 3];
            float4 b1 = *(const float4*)&Ks[kk][(tj << 3) + 4];
            float ra[8] = {a0.x, a0.y, a0.z, a0.w, a1.x, a1.y, a1.z, a1.w};
            float rb[8] = {b0.x, b0.y, b0.z, b0.w, b1.x, b1.y, b1.z, b1.w};
#pragma unroll
            for (int a = 0; a < 8; ++a)
#pragma unroll
                for (int b = 0; b < 8; ++b) acc[a][b] += ra[a] * rb[b];
        }
        __syncthreads();
    }
#pragma unroll
    for (int a = 0; a < 8; ++a) {
#pragma unroll
        for (int b = 0; b < 8; ++b) {
            int r = (ti << 3) + a;
            int i = t * 128 + r;
            int c = cbase + (tj << 3) + b;
            int j = j0 + c;
            float s = acc[a][b] * 0.125f;
            if (j < 0 || j >= S_LEN || (i - j) > 128 || (j - i) > 128) s = -1e9f;
            sc[(size_t)((h * NT + t) * 128 + r) * WIN + c] = s;
        }
    }
}

// ---------------- softmax per window row; writes full attn row (or sc fallback) ----------------
__global__ __launch_bounds__(256) void softmax_kernel(
    float* __restrict__ sc, float* __restrict__ attn, int has_attn)
{
    const int warp = threadIdx.x >> 5, lane = threadIdx.x & 31;
    const int row = blockIdx.x * 8 + warp;       // 0..32767
    const int h = row >> 11;
    const int i = row & 2047;
    float* srow = sc + (size_t)row * WIN;
    float v[12];
    float mx = -3.0e38f;
#pragma unroll
    for (int u = 0; u < 12; ++u) { v[u] = srow[lane + (u << 5)]; mx = fmaxf(mx, v[u]); }
#pragma unroll
    for (int o = 16; o; o >>= 1) mx = fmaxf(mx, __shfl_xor_sync(0xffffffffu, mx, o));
    float sum = 0.f;
#pragma unroll
    for (int u = 0; u < 12; ++u) { v[u] = expf(v[u] - mx); sum += v[u]; }
#pragma unroll
    for (int o = 16; o; o >>= 1) sum += __shfl_xor_sync(0xffffffffu, sum, o);
    const float inv = 1.0f / sum;
    const int t = i >> 7;
    const int j0 = t * 128 - 128;

    if (has_attn) {
        float* arow = attn + ((size_t)h * S_LEN + i) * S_LEN;
        float4* arow4 = (float4*)arow;
        const float4 z4 = make_float4(0.f, 0.f, 0.f, 0.f);
        int z1 = (j0 > 0 ? j0 : 0) >> 2;                       // zeros [0, z1*4)
        int z2 = ((j0 + WIN < S_LEN) ? (j0 + WIN) : S_LEN) >> 2; // zeros [z2*4, 2048)
        for (int c4 = lane; c4 < z1; c4 += 32) arow4[c4] = z4;
        for (int c4 = z2 + lane; c4 < S_LEN / 4; c4 += 32) arow4[c4] = z4;
#pragma unroll
        for (int u = 0; u < 12; ++u) {
            int j = j0 + lane + (u << 5);
            if (j >= 0 && j < S_LEN) arow[j] = v[u] * inv;
        }
    } else {
#pragma unroll
        for (int u = 0; u < 12; ++u) srow[lane + (u << 5)] = v[u] * inv;
    }
}

// ---------------- PV: ctx_tile = P_window @ V_band (P read from attn band) ----------------
__global__ __launch_bounds__(256) void pv_kernel(
    const float* __restrict__ sc, const float* __restrict__ attn,
    const float* __restrict__ vp, float* __restrict__ ctx, int has_attn)
{
    __shared__ float Ps[32][132];
    __shared__ float Vs[32][68];
    const int tid = threadIdx.x;
    const int t = blockIdx.x, h = blockIdx.y;
    const int j0 = t * 128 - 128;
    const int ti = tid >> 4, tj = tid & 15;
    float acc[8][4];
#pragma unroll
    for (int a = 0; a < 8; ++a)
#pragma unroll
        for (int b = 0; b < 4; ++b) acc[a][b] = 0.f;

    for (int k0 = 0; k0 < WIN; k0 += 32) {
#pragma unroll
        for (int u = 0; u < 4; ++u) {
            int idx = tid + (u << 8);
            int i = idx >> 3; int kq = (idx & 7) << 2;
            float4 val;
            if (has_attn) {
                int j = j0 + k0 + kq;
                val = make_float4(0.f, 0.f, 0.f, 0.f);
                if (j >= 0 && j < S_LEN)
                    val = *(const float4*)(attn + ((size_t)h * S_LEN + t * 128 + i) * S_LEN + j);
            } else {
                val = *(const float4*)(sc + (size_t)((h * NT + t) * 128 + i) * WIN + k0 + kq);
            }
            Ps[kq + 0][i] = val.x; Ps[kq + 1][i] = val.y;
            Ps[kq + 2][i] = val.z; Ps[kq + 3][i] = val.w;
        }
#pragma unroll
        for (int u = 0; u < 2; ++u) {
            int idx = tid + (u << 8);
            int kk = idx >> 4; int nq = (idx & 15) << 2;
            int j = j0 + k0 + kk;
            float4 val = make_float4(0.f, 0.f, 0.f, 0.f);
            if (j >= 0 && j < S_LEN)
                val = *(const float4*)(vp + (size_t)(h * S_LEN + j) * DEPTH + nq);
            *(float4*)&Vs[kk][nq] = val;
        }
        __syncthreads();
#pragma unroll
        for (int kk = 0; kk < 32; ++kk) {
            float4 a0 = *(const float4*)&Ps[kk][ti << 3];
            float4 a1 = *(const float4*)&Ps[kk][(ti << 3) + 4];
            float4 b  = *(const float4*)&Vs[kk][tj << 2];
            float ra[8] = {a0.x, a0.y, a0.z, a0.w, a1.x, a1.y, a1.z, a1.w};
            float rb[4] = {b.x, b.y, b.z, b.w};
#pragma unroll
            for (int a = 0; a < 8; ++a)
#pragma unroll
                for (int bb = 0; bb < 4; ++bb) acc[a][bb] += ra[a] * rb[bb];
        }
        __syncthreads();
    }
#pragma unroll
    for (int a = 0; a < 8; ++a) {
#pragma unroll
        for (int b = 0; b < 4; ++b) {
            int i = t * 128 + (ti << 3) + a;
            int n = h * DEPTH + (tj << 2) + b;
            ctx[(size_t)i * DM + n] = f2tf_f(acc[a][b]);
        }
    }
}

// ---------------- launch ----------------
extern "C" void kernel_launch(void* const* d_in, const int* in_sizes, int n_in,
                              void* d_out, int out_size)
{
    const float* x    = (const float*)d_in[0];
    const float* wqw  = (const float*)d_in[1];
    const float* wqb  = (const float*)d_in[2];
    const float* wkw  = (const float*)d_in[3];
    const float* wkb  = (const float*)d_in[4];
    const float* wvw  = (const float*)d_in[5];
    const float* wvb  = (const float*)d_in[6];
    const float* fcw  = (const float*)d_in[7];
    const float* fcb  = (const float*)d_in[8];
    const float* ff1w = (const float*)d_in[9];
    const float* ff1b = (const float*)d_in[10];
    const float* ff2w = (const float*)d_in[11];
    const float* ff2b = (const float*)d_in[12];
    const float* ln1g = (const float*)d_in[13];
    const float* ln1b = (const float*)d_in[14];
    const float* ln2g = (const float*)d_in[15];
    const float* ln2b = (const float*)d_in[16];

    float* out = (float*)d_out;
    const int has_attn = (out_size > S_LEN * DM) ? 1 : 0;
    float* attn = out + (size_t)S_LEN * DM;

    float *xn, *q, *k, *v, *sc, *ctx, *x2, *xn2, *h1, *part;
    float *wq, *wk, *wv, *wfc, *wf1, *wf2;
    cudaGetSymbolAddress((void**)&xn,  g_xn);
    cudaGetSymbolAddress((void**)&q,   g_q);
    cudaGetSymbolAddress((void**)&k,   g_k);
    cudaGetSymbolAddress((void**)&v,   g_v);
    cudaGetSymbolAddress((void**)&sc,  g_sc);
    cudaGetSymbolAddress((void**)&ctx, g_ctx);
    cudaGetSymbolAddress((void**)&x2,  g_x2);
    cudaGetSymbolAddress((void**)&xn2, g_xn2);
    cudaGetSymbolAddress((void**)&h1,  g_h1);
    cudaGetSymbolAddress((void**)&part, g_part);
    cudaGetSymbolAddress((void**)&wq,  g_wq);
    cudaGetSymbolAddress((void**)&wk,  g_wk);
    cudaGetSymbolAddress((void**)&wv,  g_wv);
    cudaGetSymbolAddress((void**)&wfc, g_wfc);
    cudaGetSymbolAddress((void**)&wf1, g_wf1);
    cudaGetSymbolAddress((void**)&wf2, g_wf2);

    // round weights to tf32 once per launch
    round_kernel<<<1024, 256>>>((const float4*)wqw,  (float4*)wq,  DM*DM/4);
    round_kernel<<<1024, 256>>>((const float4*)wkw,  (float4*)wk,  DM*DM/4);
    round_kernel<<<1024, 256>>>((const float4*)wvw,  (float4*)wv,  DM*DM/4);
    round_kernel<<<1024, 256>>>((const float4*)fcw,  (float4*)wfc, DM*DM/4);
    round_kernel<<<1024, 256>>>((const float4*)ff1w, (float4*)wf1, DM*FF/4);
    round_kernel<<<1024, 256>>>((const float4*)ff2w, (float4*)wf2, FF*DM/4);

    ln_kernel<<<S_LEN, 256>>>(x, ln1g, ln1b, xn);

    // fused QKV (grid.z selects weight)
    gemm_tf32<<<dim3(DM/128, S_LEN/128, 3), 256>>>(
        xn, wq, wk, wv, wqb, wkb, wvb, q, k, v, S_LEN, DM, DM, DM, MODE_SPLIT);

    scores_kernel<<<dim3(3, NT, NH), 256>>>(q, k, sc);
    softmax_kernel<<<NH * NT * 128 / 8, 256>>>(sc, attn, has_attn);
    pv_kernel<<<dim3(NT, NH), 256>>>(sc, attn, v, ctx, has_attn);

    // fc: split-K=2 partials + combine with residual x
    gemm_tf32<<<dim3(DM/128, S_LEN/128, 2), 256>>>(
        ctx, wfc, wfc, wfc, fcb, fcb, fcb, part, part, part,
        S_LEN, DM, DM/2, DM, MODE_PART);
    combine_kernel<<<1024, 256>>>((const float4*)part, (const float4*)fcb,
                                  (const float4*)x, (float4*)x2, S_LEN*DM/4, DM/4);

    ln_kernel<<<S_LEN, 256>>>(x2, ln2g, ln2b, xn2);

    // ff1 + gelu (grid 512)
    gemm_tf32<<<dim3(FF/128, S_LEN/128, 1), 256>>>(
        xn2, wf1, wf1, wf1, ff1b, ff1b, ff1b, h1, h1, h1,
        S_LEN, FF, DM, DM, MODE_GELU);

    // ff2: split-K=2 partials + combine with residual x2 -> final out
    gemm_tf32<<<dim3(DM/128, S_LEN/128, 2), 256>>>(
        h1, wf2, wf2, wf2, ff2b, ff2b, ff2b, part, part, part,
        S_LEN, DM, FF/2, FF, MODE_PART);
    combine_kernel<<<1024, 256>>>((const float4*)part, (const float4*)ff2b,
                                  (const float4*)x2, (float4*)out, S_LEN*DM/4, DM/4);
}